// round 8
// baseline (speedup 1.0000x reference)
#include <cuda_runtime.h>
#include <cuda_bf16.h>

// Fixed problem shapes
#define N_C 500000
#define N_F 2000000
#define KNBR 8
#define ROWW (KNBR + 2)   // 8 neighbor cols + pad + count (ints)
#define TPB 256

// Scratch: d = input - pred, padded to float4 (16B-aligned single-sector gathers).
__device__ float4 g_d[N_C + N_F];
__device__ double g_acc;
__device__ unsigned int g_count;

// ---------------------------------------------------------------------------
// Kernel 1: d = input - pred for both meshes (float4 loads + smem transpose).
// Also resets the reduction accumulator/counter (runs fully before loss).
// ---------------------------------------------------------------------------
__global__ void diff_kernel(const float* __restrict__ ci,
                            const float* __restrict__ cp,
                            const float* __restrict__ fi,
                            const float* __restrict__ fp,
                            int nc, int nf, int cbd) {
    const int t = threadIdx.x;
    const int b = blockIdx.x;
    if (b == 0 && t == 0) { g_acc = 0.0; g_count = 0u; }

    const float* __restrict__ a;
    const float* __restrict__ p;
    int n, segbase, v0;
    if (b < cbd) { a = ci; p = cp; n = nc; segbase = 0;  v0 = b * TPB; }
    else         { a = fi; p = fp; n = nf; segbase = nc; v0 = (b - cbd) * TPB; }

    __shared__ float s[3 * TPB];

    if (v0 + TPB <= n) {
        // Full block: 256 vertices = 768 floats = 192 float4 per array.
        const int f4base = (v0 >> 2) * 3;  // exact: v0 % 4 == 0
        if (t < 3 * TPB / 4) {
            float4 av = __ldcs((const float4*)a + f4base + t);
            float4 pv = __ldcs((const float4*)p + f4base + t);
            ((float4*)s)[t] = make_float4(av.x - pv.x, av.y - pv.y,
                                          av.z - pv.z, av.w - pv.w);
        }
        __syncthreads();
        // stride-3 smem reads: gcd(3,32)=1 -> conflict-free
        g_d[segbase + v0 + t] =
            make_float4(s[3 * t], s[3 * t + 1], s[3 * t + 2], 0.0f);
    } else {
        const int i = v0 + t;
        if (i < n) {
            const int base = 3 * i;
            g_d[segbase + i] = make_float4(a[base + 0] - p[base + 0],
                                           a[base + 1] - p[base + 1],
                                           a[base + 2] - p[base + 2], 0.0f);
        }
    }
}

// ---------------------------------------------------------------------------
// Kernel 2: fused loss for both meshes + last-block finalize.
// idx rows are staged through shared memory with coalesced int2 loads
// (10 L1 wavefronts/warp instead of 50 for strided per-thread row loads).
// ---------------------------------------------------------------------------
__global__ void loss_kernel(const int* __restrict__ lic,
                            const int* __restrict__ lif,
                            int nc, int nf, int cb,
                            double sc, double sf,
                            float* __restrict__ out) {
    const int b = blockIdx.x;
    const int t = threadIdx.x;

    const int* __restrict__ lap;
    int n, base, v0;
    double scale;
    if (b < cb) { lap = lic; n = nc; base = 0;  scale = sc; v0 = b * TPB; }
    else        { lap = lif; n = nf; base = nc; scale = sf; v0 = (b - cb) * TPB; }

    __shared__ int s_idx[TPB * ROWW];           // 10240 B row staging
    __shared__ float warp_sums[TPB / 32];
    __shared__ bool is_last;

    // --- coalesced staging of this block's idx rows ---
    const int m = min(TPB, n - v0);             // vertices in this block
    {
        const int2* __restrict__ src = (const int2*)(lap) + (size_t)v0 * 5;
        int2* dst = (int2*)s_idx;
        const int tot = m * 5;                  // int2 count (exact, no overread)
        for (int k = t; k < tot; k += TPB)
            dst[k] = __ldcs(src + k);
    }
    __syncthreads();

    float v = 0.0f;
    if (t < m) {
        const float4* __restrict__ d = g_d + base;
        const int i = v0 + t;
        const float4 di = d[i];

        const int* row = s_idx + t * ROWW;      // stride-10 words: 2-way conflicts
        int idx[KNBR];
#pragma unroll
        for (int j = 0; j < KNBR; j++) idx[j] = row[j];
        const int cnt = row[KNBR + 1];

        float sx = 0.0f, sy = 0.0f, sz = 0.0f;
#pragma unroll
        for (int j = 0; j < KNBR; j++) {
            const int id = idx[j];
            if (id >= 0) {
                const float4 nv = d[id];
                sx += nv.x; sy += nv.y; sz += nv.z;
            }
        }
        const float inv = 1.0f / (float)cnt;
        const float ex = di.x - sx * inv;
        const float ey = di.y - sy * inv;
        const float ez = di.z - sz * inv;
        v = ex * ex + ey * ey + ez * ez;
    }

    // --- intra-block reduction ---
#pragma unroll
    for (int off = 16; off > 0; off >>= 1)
        v += __shfl_down_sync(0xFFFFFFFFu, v, off);

    const int lane = t & 31;
    const int wid  = t >> 5;
    if (lane == 0) warp_sums[wid] = v;
    __syncthreads();

    if (wid == 0) {
        float s = (lane < (TPB >> 5)) ? warp_sums[lane] : 0.0f;
#pragma unroll
        for (int off = 4; off > 0; off >>= 1)
            s += __shfl_down_sync(0xFFFFFFFFu, s, off);
        if (lane == 0) {
            atomicAdd(&g_acc, (double)s * scale);
            __threadfence();
            unsigned int old = atomicAdd(&g_count, 1u);
            is_last = (old == gridDim.x - 1u);
        }
    }
    __syncthreads();

    if (is_last && t == 0) {
        __threadfence();
        out[0] = (float)g_acc;
    }
}

extern "C" void kernel_launch(void* const* d_in, const int* in_sizes, int n_in,
                              void* d_out, int out_size) {
    const float* ci = (const float*)d_in[0];  // coarse_input  (N_C,3)
    const float* cp = (const float*)d_in[1];  // coarse_pred   (N_C,3)
    const float* fi = (const float*)d_in[2];  // fine_input    (N_F,3)
    const float* fp = (const float*)d_in[3];  // fine_pred     (N_F,3)
    const int* lic  = (const int*)d_in[4];    // lap_idx_coarse (N_C,10)
    const int* lif  = (const int*)d_in[5];    // lap_idx_fine   (N_F,10)

    const int nc = in_sizes[0] / 3;
    const int nf = in_sizes[2] / 3;

    const int cb = (nc + TPB - 1) / TPB;
    const int fb = (nf + TPB - 1) / TPB;

    diff_kernel<<<cb + fb, TPB>>>(ci, cp, fi, fp, nc, nf, cb);
    loss_kernel<<<cb + fb, TPB>>>(lic, lif, nc, nf, cb,
                                  0.5 / (double)nc, 0.5 / (double)nf,
                                  (float*)d_out);
}

// round 9
// speedup vs baseline: 1.0613x; 1.0613x over previous
#include <cuda_runtime.h>
#include <cuda_bf16.h>

// Fixed problem shapes
#define N_C 500000
#define N_F 2000000
#define KNBR 8
#define TPB 256

// Scratch: d = input - pred, padded to float4 (16B-aligned single-sector gathers).
__device__ float4 g_d[N_C + N_F];
__device__ double g_acc;
__device__ unsigned int g_b1, g_b2, g_b3;   // zero-initialized; reset by last block

// ---------------------------------------------------------------------------
// Grid-wide spin barrier. Safe only because grid == SMs*4 and
// __launch_bounds__(256,4) guarantees all blocks are co-resident.
// ---------------------------------------------------------------------------
__device__ __forceinline__ void grid_barrier(unsigned int* ctr, unsigned int expected) {
    __syncthreads();
    if (threadIdx.x == 0) {
        __threadfence();
        atomicAdd(ctr, 1u);
        while (*(volatile unsigned int*)ctr < expected) __nanosleep(64);
        __threadfence();
    }
    __syncthreads();
}

// ---------------------------------------------------------------------------
// diff for one 256-vertex tile: d = input - pred, float4 loads + smem transpose.
// ---------------------------------------------------------------------------
__device__ __forceinline__ void diff_tile(const float* __restrict__ a,
                                          const float* __restrict__ p,
                                          int n, int segbase, int tile,
                                          float* s /*768 floats smem*/) {
    const int t = threadIdx.x;
    const int v0 = tile * TPB;
    if (v0 + TPB <= n) {                       // uniform per block
        const int f4base = (v0 >> 2) * 3;      // exact: v0 % 4 == 0
        if (t < 3 * TPB / 4) {
            float4 av = ((const float4*)a)[f4base + t];
            float4 pv = ((const float4*)p)[f4base + t];
            ((float4*)s)[t] = make_float4(av.x - pv.x, av.y - pv.y,
                                          av.z - pv.z, av.w - pv.w);
        }
        __syncthreads();
        // stride-3 smem reads: gcd(3,32)=1 -> conflict-free
        g_d[segbase + v0 + t] =
            make_float4(s[3 * t], s[3 * t + 1], s[3 * t + 2], 0.0f);
        __syncthreads();                       // s reused next iteration
    } else {
        const int i = v0 + t;
        if (i < n) {
            const int b3 = 3 * i;
            g_d[segbase + i] = make_float4(a[b3] - p[b3], a[b3 + 1] - p[b3 + 1],
                                           a[b3 + 2] - p[b3 + 2], 0.0f);
        }
    }
}

// ---------------------------------------------------------------------------
// Per-vertex Laplacian-difference squared norm (R5-style direct loads).
// ---------------------------------------------------------------------------
__device__ __forceinline__ float loss_vertex(const int* __restrict__ lap,
                                             const float4* __restrict__ d,
                                             int n, int tile) {
    const int i = tile * TPB + threadIdx.x;
    if (i >= n) return 0.0f;
    const float4 di = d[i];

    // 40B row = 5 x int2 (8B aligned)
    const int2* __restrict__ r2 = (const int2*)lap + (size_t)i * 5;
    const int2 p0 = r2[0], p1 = r2[1], p2 = r2[2], p3 = r2[3], p4 = r2[4];
    int idx[KNBR] = {p0.x, p0.y, p1.x, p1.y, p2.x, p2.y, p3.x, p3.y};

    float sx = 0.0f, sy = 0.0f, sz = 0.0f;
#pragma unroll
    for (int j = 0; j < KNBR; j++) {
        const int id = idx[j];
        if (id >= 0) {
            const float4 nv = d[id];
            sx += nv.x; sy += nv.y; sz += nv.z;
        }
    }
    const float inv = 1.0f / (float)p4.y;      // p4.y = count
    const float ex = di.x - sx * inv;
    const float ey = di.y - sy * inv;
    const float ez = di.z - sz * inv;
    return ex * ex + ey * ey + ez * ez;
}

// Block reduction + scaled atomic into g_acc.
__device__ __forceinline__ void block_add(float v, double scale, float* wsum) {
#pragma unroll
    for (int o = 16; o > 0; o >>= 1)
        v += __shfl_down_sync(0xFFFFFFFFu, v, o);
    const int lane = threadIdx.x & 31;
    const int wid  = threadIdx.x >> 5;
    if (lane == 0) wsum[wid] = v;
    __syncthreads();
    if (wid == 0) {
        float s = (lane < (TPB >> 5)) ? wsum[lane] : 0.0f;
#pragma unroll
        for (int o = 4; o > 0; o >>= 1)
            s += __shfl_down_sync(0xFFFFFFFFu, s, o);
        if (lane == 0) atomicAdd(&g_acc, (double)s * scale);
    }
    __syncthreads();
}

// ---------------------------------------------------------------------------
// Single persistent kernel:
//   phase1: diff_coarse | barrier | phase2: loss_coarse + diff_fine (mixed)
//   | barrier | phase3: loss_fine | last block finalizes + resets state.
// ---------------------------------------------------------------------------
__global__ void __launch_bounds__(TPB, 4)
fused_kernel(const float* __restrict__ ci, const float* __restrict__ cp,
             const float* __restrict__ fi, const float* __restrict__ fp,
             const int* __restrict__ lic, const int* __restrict__ lif,
             int nc, int nf, double sc, double sf, float* __restrict__ out) {
    __shared__ float s[3 * TPB];
    __shared__ float wsum[TPB / 32];
    __shared__ bool last;

    const unsigned G = gridDim.x;
    const unsigned tc = (unsigned)((nc + TPB - 1) / TPB);
    const unsigned tf = (unsigned)((nf + TPB - 1) / TPB);

    // ---- phase 1: diff coarse ----
    for (unsigned w = blockIdx.x; w < tc; w += G)
        diff_tile(ci, cp, nc, 0, (int)w, s);
    grid_barrier(&g_b1, G);

    // ---- phase 2: loss coarse overlapped with diff fine ----
    float accc = 0.0f;
    const unsigned tot2 = tc + tf;
    for (unsigned w = blockIdx.x; w < tot2; w += G) {
        if (w < tc) accc += loss_vertex(lic, g_d, nc, (int)w);
        else        diff_tile(fi, fp, nf, nc, (int)(w - tc), s);
    }
    block_add(accc, sc, wsum);
    grid_barrier(&g_b2, G);

    // ---- phase 3: loss fine ----
    float accf = 0.0f;
    for (unsigned w = blockIdx.x; w < tf; w += G)
        accf += loss_vertex(lif, g_d + nc, nf, (int)w);
    block_add(accf, sf, wsum);

    // ---- finalize: last block writes result and resets all state ----
    if (threadIdx.x == 0) {
        __threadfence();
        unsigned old = atomicAdd(&g_b3, 1u);
        last = (old == G - 1u);
    }
    __syncthreads();
    if (last && threadIdx.x == 0) {
        __threadfence();
        out[0] = (float)g_acc;
        g_acc = 0.0;                 // replay-safe reset
        g_b1 = 0u; g_b2 = 0u; g_b3 = 0u;
        __threadfence();
    }
}

extern "C" void kernel_launch(void* const* d_in, const int* in_sizes, int n_in,
                              void* d_out, int out_size) {
    const float* ci = (const float*)d_in[0];  // coarse_input  (N_C,3)
    const float* cp = (const float*)d_in[1];  // coarse_pred   (N_C,3)
    const float* fi = (const float*)d_in[2];  // fine_input    (N_F,3)
    const float* fp = (const float*)d_in[3];  // fine_pred     (N_F,3)
    const int* lic  = (const int*)d_in[4];    // lap_idx_coarse (N_C,10)
    const int* lif  = (const int*)d_in[5];    // lap_idx_fine   (N_F,10)

    const int nc = in_sizes[0] / 3;
    const int nf = in_sizes[2] / 3;

    int sm = 148;
    cudaDeviceGetAttribute(&sm, cudaDevAttrMultiProcessorCount, 0);
    const int grid = sm * 4;   // matches __launch_bounds__(TPB,4): all co-resident

    fused_kernel<<<grid, TPB>>>(ci, cp, fi, fp, lic, lif, nc, nf,
                                0.5 / (double)nc, 0.5 / (double)nf,
                                (float*)d_out);
}